// round 14
// baseline (speedup 1.0000x reference)
#include <cuda_runtime.h>
#include <cstdint>

#define Bz   256
#define Tz   512
#define Ez   200
#define Hz   100
#define NCz  5
#define BT   131072      // B*T

typedef unsigned long long ull;

// ---------------- scratch ----------------
__device__ float g_scale[BT];
__device__ float g_xp[(size_t)BT * 300];   // 157 MB
__device__ float g_rnn[(size_t)BT * 100];  // 52 MB
__device__ float g_ti[(size_t)BT * 100];   // 52 MB
__device__ float g_z[BT];
__device__ float g_li[BT];
__device__ float g_state[Bz * Hz];

// ---------------- helpers ----------------
__device__ __forceinline__ float sigf(float x) {
    return 1.0f / (1.0f + __expf(-x));
}
__device__ __forceinline__ float tanh_fast(float x) {
    float t = __expf(-2.0f * fabsf(x));
    float r = (1.0f - t) / (1.0f + t);
    return copysignf(r, x);
}
__device__ __forceinline__ float to_tf32(float x) {
    uint32_t u;
    asm("cvt.rna.tf32.f32 %0, %1;" : "=r"(u) : "f"(x));
    return __uint_as_float(u);
}
__device__ __forceinline__ void fma2(ull& d, ull a, ull b) {
    asm("fma.rn.f32x2 %0, %1, %2, %0;" : "+l"(d) : "l"(a), "l"(b));
}
__device__ __forceinline__ float upksum(ull v) {
    float lo, hi;
    asm("mov.b64 {%0,%1}, %2;" : "=f"(lo), "=f"(hi) : "l"(v));
    return lo + hi;
}

// ---------------- K1: per-row embedding norm scale ----------------
__global__ void __launch_bounds__(256) scale_kernel(const int* __restrict__ txt,
                                                    const float* __restrict__ emb) {
    int warp = (blockIdx.x * 256 + threadIdx.x) >> 5;
    int lane = threadIdx.x & 31;
    if (warp >= BT) return;
    int tok = txt[warp];
    const float* row = emb + (size_t)tok * Ez;
    float ss = 0.f;
    for (int k = lane; k < Ez; k += 32) { float v = row[k]; ss += v * v; }
    #pragma unroll
    for (int o = 16; o > 0; o >>= 1) ss += __shfl_xor_sync(0xffffffffu, ss, o);
    if (lane == 0) {
        float n = sqrtf(ss);
        g_scale[warp] = (n > 1.0f) ? 1.0f / (n + 1e-7f) : 1.0f;
    }
}

// ---------------- dummy (keeps ncu capture slot on gru_kernel) ----------------
__global__ void dummy_kernel() {}

// ---------------- K2/K5: tf32 MMA GEMM ----------------
template <int KDIM, int KCEIL, int KSTR, int TN, int WNc, bool GATHER>
__global__ void __launch_bounds__(256) mma_gemm_kernel(
    const float* __restrict__ Ain,
    const int* __restrict__ txt,
    const float* __restrict__ emb,
    const float* __restrict__ W,
    const float* __restrict__ bias,
    float* __restrict__ C,
    int NV)
{
    extern __shared__ float sm[];
    float* As = sm;
    float* Bs = sm + 64 * KSTR;
    __shared__ int   s_tok[64];
    __shared__ float s_scl[64];

    const int tid   = threadIdx.x;
    const int rbase = blockIdx.x * 64;
    const int nbase = blockIdx.y * TN;

    if (GATHER) {
        if (tid < 64) {
            int r = rbase + tid;
            s_tok[tid] = txt[r];
            s_scl[tid] = g_scale[r];
        }
        __syncthreads();
    }

    const int K4 = KCEIL / 4;
    for (int e = tid; e < 64 * K4; e += 256) {
        int row = e / K4, k4 = e % K4;
        float4 v = make_float4(0.f, 0.f, 0.f, 0.f);
        if (4 * k4 + 3 < KDIM) {
            if (GATHER) {
                const float4* p = (const float4*)(emb + (size_t)s_tok[row] * KDIM) + k4;
                v = *p;
                float s = s_scl[row];
                v.x *= s; v.y *= s; v.z *= s; v.w *= s;
            } else {
                const float4* p = (const float4*)(Ain + (size_t)(rbase + row) * KDIM) + k4;
                v = *p;
            }
        }
        float4 o = make_float4(to_tf32(v.x), to_tf32(v.y), to_tf32(v.z), to_tf32(v.w));
        *(float4*)(As + row * KSTR + 4 * k4) = o;
    }
    for (int e = tid; e < TN * K4; e += 256) {
        int n = e / K4, k4 = e % K4;
        int ng = nbase + n;
        float4 v = make_float4(0.f, 0.f, 0.f, 0.f);
        if (ng < NV && 4 * k4 + 3 < KDIM) {
            const float4* p = (const float4*)(W + (size_t)ng * KDIM) + k4;
            v = *p;
        }
        float4 o = make_float4(to_tf32(v.x), to_tf32(v.y), to_tf32(v.z), to_tf32(v.w));
        *(float4*)(Bs + n * KSTR + 4 * k4) = o;
    }
    __syncthreads();

    const int wid  = tid >> 5;
    const int lane = tid & 31;
    const int g    = lane >> 2;
    const int tg   = lane & 3;
    const int mwarp = wid & 1;
    const int nwarp = wid >> 1;
    const int NF = WNc / 8;

    float c[2][NF][4];
    #pragma unroll
    for (int mt = 0; mt < 2; mt++)
        #pragma unroll
        for (int nf = 0; nf < NF; nf++)
            #pragma unroll
            for (int i = 0; i < 4; i++) c[mt][nf][i] = 0.f;

    const float* Aw = As + (mwarp * 32) * KSTR;
    const float* Bw = Bs + (nwarp * WNc) * KSTR;

    #pragma unroll 1
    for (int k8 = 0; k8 < KCEIL / 8; k8++) {
        int k0 = k8 * 8;
        uint32_t a[2][4], b[NF][2];
        #pragma unroll
        for (int mt = 0; mt < 2; mt++) {
            const float* ap = Aw + (mt * 16 + g) * KSTR + k0 + tg;
            a[mt][0] = __float_as_uint(ap[0]);
            a[mt][1] = __float_as_uint(ap[8 * KSTR]);
            a[mt][2] = __float_as_uint(ap[4]);
            a[mt][3] = __float_as_uint(ap[8 * KSTR + 4]);
        }
        #pragma unroll
        for (int nf = 0; nf < NF; nf++) {
            const float* bp = Bw + (nf * 8 + g) * KSTR + k0 + tg;
            b[nf][0] = __float_as_uint(bp[0]);
            b[nf][1] = __float_as_uint(bp[4]);
        }
        #pragma unroll
        for (int mt = 0; mt < 2; mt++)
            #pragma unroll
            for (int nf = 0; nf < NF; nf++) {
                asm volatile(
                    "mma.sync.aligned.m16n8k8.row.col.f32.tf32.tf32.f32 "
                    "{%0,%1,%2,%3}, {%4,%5,%6,%7}, {%8,%9}, {%0,%1,%2,%3};"
                    : "+f"(c[mt][nf][0]), "+f"(c[mt][nf][1]),
                      "+f"(c[mt][nf][2]), "+f"(c[mt][nf][3])
                    : "r"(a[mt][0]), "r"(a[mt][1]), "r"(a[mt][2]), "r"(a[mt][3]),
                      "r"(b[nf][0]), "r"(b[nf][1]));
            }
    }

    #pragma unroll
    for (int mt = 0; mt < 2; mt++) {
        int row = rbase + mwarp * 32 + mt * 16 + g;
        #pragma unroll
        for (int nf = 0; nf < NF; nf++) {
            int col = nbase + nwarp * WNc + nf * 8 + 2 * tg;
            if (col < NV) {
                float b0 = bias[col], b1 = bias[col + 1];
                float2 v0 = make_float2(c[mt][nf][0] + b0, c[mt][nf][1] + b1);
                float2 v1 = make_float2(c[mt][nf][2] + b0, c[mt][nf][3] + b1);
                *(float2*)(C + (size_t)row * NV + col) = v0;
                *(float2*)(C + (size_t)(row + 8) * NV + col) = v1;
            }
        }
    }
}

// ============================================================================
// K3: GRU scan v5 — warp-granular k-split (unchanged from best). 128 blocks,
// 640 threads: warps 0-9 half 0 (row=tid), warps 10-19 half 1 (row=tid-320).
// ============================================================================
__global__ void __launch_bounds__(640, 1) gru_kernel(const float* __restrict__ Whh,
                                                     const float* __restrict__ bhh) {
    __shared__ __align__(16) float hsh[2][104];     // [batch][k]
    __shared__ float ph[2][2][304];                 // [half][batch][row]
    const int tid = threadIdx.x;
    const int b0 = blockIdx.x * 2;
    const float* x0 = g_xp + (size_t)b0 * Tz * 300;
    const float* x1 = x0 + (size_t)Tz * 300;

    const int half = (tid >= 320) ? 1 : 0;
    const int row  = tid - half * 320;              // 0..319
    const int rcl  = (row < 300) ? row : 299;
    const bool act = (row < 300);

    if (tid < 104) { hsh[0][tid] = 0.f; hsh[1][tid] = 0.f; }

    ull ws, wv[24];
    {
        const ull* p = (const ull*)(Whh + rcl * 100 + half * 50);
        if (half == 0) {
            ws = p[24];
            #pragma unroll
            for (int q = 0; q < 24; q++) wv[q] = p[q];
        } else {
            ws = p[0];
            #pragma unroll
            for (int q = 0; q < 24; q++) wv[q] = p[1 + q];
        }
    }
    const int sidx = half ? 25 : 24;
    const int vec0 = half ? 26 : 0;
    float bias_r = (half == 0) ? bhh[rcl] : 0.f;

    float xr0 = 0.f, xz0 = 0.f, xn0 = 0.f, xr1 = 0.f, xz1 = 0.f, xn1 = 0.f;
    if (tid < 100) {
        xr0 = x0[tid]; xz0 = x0[100 + tid]; xn0 = x0[200 + tid];
        xr1 = x1[tid]; xz1 = x1[100 + tid]; xn1 = x1[200 + tid];
    }
    __syncthreads();

    for (int t = 0; t < Tz; t++) {
        float nr0 = 0.f, nz0 = 0.f, nn0 = 0.f, nr1 = 0.f, nz1 = 0.f, nn1 = 0.f;
        if (tid < 100 && t + 1 < Tz) {
            const float* p0 = x0 + (size_t)(t + 1) * 300;
            const float* p1 = x1 + (size_t)(t + 1) * 300;
            nr0 = p0[tid]; nz0 = p0[100 + tid]; nn0 = p0[200 + tid];
            nr1 = p1[tid]; nz1 = p1[100 + tid]; nn1 = p1[200 + tid];
        }
        {
            const ull* B0 = (const ull*)&hsh[0][0];
            const ull* B1 = B0 + 52;
            ull a0 = 0ull, d0 = 0ull, a1 = 0ull, d1 = 0ull;
            fma2(a0, ws, B0[sidx]);
            fma2(a1, ws, B1[sidx]);
            const ulonglong2* V0 = (const ulonglong2*)(B0 + vec0);
            const ulonglong2* V1 = (const ulonglong2*)(B1 + vec0);
            #pragma unroll
            for (int q = 0; q < 12; q++) {
                ulonglong2 h0 = V0[q], h1 = V1[q];
                fma2(a0, wv[2 * q],     h0.x);
                fma2(d0, wv[2 * q + 1], h0.y);
                fma2(a1, wv[2 * q],     h1.x);
                fma2(d1, wv[2 * q + 1], h1.y);
            }
            if (act) {
                ph[half][0][row] = upksum(a0) + upksum(d0) + bias_r;
                ph[half][1][row] = upksum(a1) + upksum(d1) + bias_r;
            }
        }
        __syncthreads();
        if (tid < 100) {
            int j = tid;
            float hr0 = ph[0][0][j]       + ph[1][0][j];
            float hz0 = ph[0][0][100 + j] + ph[1][0][100 + j];
            float hn0 = ph[0][0][200 + j] + ph[1][0][200 + j];
            float hr1 = ph[0][1][j]       + ph[1][1][j];
            float hz1 = ph[0][1][100 + j] + ph[1][1][100 + j];
            float hn1 = ph[0][1][200 + j] + ph[1][1][200 + j];
            float ho0 = hsh[0][j], ho1 = hsh[1][j];
            float r0 = sigf(xr0 + hr0), r1 = sigf(xr1 + hr1);
            float z0 = sigf(xz0 + hz0), z1 = sigf(xz1 + hz1);
            float n0 = tanh_fast(xn0 + r0 * hn0);
            float n1 = tanh_fast(xn1 + r1 * hn1);
            float hx = (1.f - z0) * n0 + z0 * ho0;
            float hy = (1.f - z1) * n1 + z1 * ho1;
            hsh[0][j] = hx;
            hsh[1][j] = hy;
            g_rnn[((size_t)b0 * Tz + t) * Hz + j]       = hx;
            g_rnn[((size_t)(b0 + 1) * Tz + t) * Hz + j] = hy;
            xr0 = nr0; xz0 = nz0; xn0 = nn0;
            xr1 = nr1; xz1 = nz1; xn1 = nn1;
        }
        __syncthreads();
    }
}

// ---------------- K4: per-(b,t) z (attention gate) and lgr_in ----------------
__global__ void __launch_bounds__(256) zli_kernel(const float* __restrict__ Wlgr,
                                                  const int* __restrict__ lens) {
    int warp = (blockIdx.x * 256 + threadIdx.x) >> 5;
    int lane = threadIdx.x & 31;
    if (warp >= BT) return;
    int b = warp >> 9;
    int t = warp & (Tz - 1);
    const float* r = g_rnn + (size_t)warp * Hz;
    float s1 = 0.f, s2 = 0.f, s3 = 0.f;
    for (int k = lane; k < Hz; k += 32) {
        float v = r[k];
        s1 += v;
        s2 += v * v;
        s3 += v * Wlgr[k];
    }
    #pragma unroll
    for (int o = 16; o > 0; o >>= 1) {
        s1 += __shfl_xor_sync(0xffffffffu, s1, o);
        s2 += __shfl_xor_sync(0xffffffffu, s2, o);
        s3 += __shfl_xor_sync(0xffffffffu, s3, o);
    }
    if (lane == 0) {
        float nrm = sqrtf(s2);
        float att = 0.001f * s1 / fmaxf(nrm, 1e-12f);
        float zv = (t < lens[b] && att > 0.f) ? att : 0.f;
        g_z[warp]  = zv;
        g_li[warp] = s3;
    }
}

// ============================================================================
// K6: second recurrence v4 — k-QUARTER-split GEMV (gru-v5 structure).
// 128 blocks (2 batches), 448 threads:
//   tid 0-399 : GEMV. quarter q=tid/100 (float ranges 0/28/56/84, 16B aligned),
//       row=tid%100. w[14] ull (q3: w[8..13]=0). Both batches per thread
//       (4 chains x 7 deep). Partials -> ph[q][batch][row].
//   tid <100  : ti register pipeline (prefetch t+1 at phase-1 start) + update.
//   warp 13 (tid 416-447): gate reduction (li/z preloaded to smem).
// st buffer padded to 120 floats (104..119 zero) so q3 smem reads are uniform.
// ============================================================================
__global__ void __launch_bounds__(448, 1) rec_kernel(const float* __restrict__ Wts,
                                                     const float* __restrict__ bts,
                                                     const float* __restrict__ Wlgr,
                                                     const float* __restrict__ blgr) {
    __shared__ __align__(16) float stsh[2][120];
    __shared__ float li_sh[2][Tz];
    __shared__ float z_sh[2][Tz];
    __shared__ float ph[4][2][104];
    __shared__ float gz[4];
    const int tid = threadIdx.x;
    const int b0 = blockIdx.x * 2;

    const bool isG = (tid < 400);
    const int q   = tid / 100;       // 0..3 (garbage for tid>=400, unused)
    const int row = tid % 100;
    const int ku  = q * 14;          // ull offset: 0,14,28,42 (16B aligned)

    // preload li/z (coalesced)
    for (int i = tid; i < Tz; i += 448) {
        li_sh[0][i] = g_li[(size_t)b0 * Tz + i];
        li_sh[1][i] = g_li[(size_t)(b0 + 1) * Tz + i];
        z_sh[0][i]  = g_z[(size_t)b0 * Tz + i];
        z_sh[1][i]  = g_z[(size_t)(b0 + 1) * Tz + i];
    }
    if (tid < 120) { stsh[0][tid] = 0.f; stsh[1][tid] = 0.f; }

    // weights: 14 ulls (28 floats) of the row's k-quarter; q3 covers 16 real
    ull w[14];
    if (isG) {
        const ull* p = (const ull*)(Wts + row * 100) + ku;
        #pragma unroll
        for (int i = 0; i < 14; i++)
            w[i] = (q == 3 && i >= 8) ? 0ull : p[i];
    }

    float btsr = 0.f, tv0 = 0.f, tv1 = 0.f;
    const float* tb0 = nullptr;
    const float* tb1 = nullptr;
    if (tid < 100) {
        btsr = bts[tid];
        tb0 = g_ti + (size_t)b0 * Tz * Hz + tid;
        tb1 = g_ti + (size_t)(b0 + 1) * Tz * Hz + tid;
        tv0 = tb0[0];
        tv1 = tb1[0];
    }

    float wl4[4] = {0.f, 0.f, 0.f, 0.f};
    float blg = 0.f;
    const int glan = tid - 416;
    if (tid >= 416) {
        #pragma unroll
        for (int i = 0; i < 4; i++) {
            int k = glan + 32 * i;
            wl4[i] = (k < 100) ? Wlgr[100 + k] : 0.f;
        }
        blg = blgr[0];
    }
    __syncthreads();

    for (int t = 0; t < Tz; t++) {
        float tn0 = 0.f, tn1 = 0.f;
        if (isG) {
            if (tid < 100 && t + 1 < Tz) {       // ti prefetch (full-step budget)
                tn0 = tb0[(size_t)(t + 1) * Hz];
                tn1 = tb1[(size_t)(t + 1) * Hz];
            }
            const ulonglong2* V0 = (const ulonglong2*)((const ull*)&stsh[0][0] + ku);
            const ulonglong2* V1 = (const ulonglong2*)((const ull*)&stsh[1][0] + ku);
            ull a0 = 0ull, d0 = 0ull, a1 = 0ull, d1 = 0ull;
            #pragma unroll
            for (int i = 0; i < 7; i++) {
                ulonglong2 s0 = V0[i], s1 = V1[i];
                fma2(a0, w[2 * i],     s0.x);
                fma2(d0, w[2 * i + 1], s0.y);
                fma2(a1, w[2 * i],     s1.x);
                fma2(d1, w[2 * i + 1], s1.y);
            }
            ph[q][0][row] = upksum(a0) + upksum(d0);
            ph[q][1][row] = upksum(a1) + upksum(d1);
        } else if (tid >= 416) {
            float pg0 = 0.f, pg1 = 0.f;
            #pragma unroll
            for (int i = 0; i < 4; i++) {
                int k = glan + 32 * i;
                if (k < 100) {
                    pg0 += wl4[i] * stsh[0][k];
                    pg1 += wl4[i] * stsh[1][k];
                }
            }
            #pragma unroll
            for (int o = 16; o > 0; o >>= 1) {
                pg0 += __shfl_xor_sync(0xffffffffu, pg0, o);
                pg1 += __shfl_xor_sync(0xffffffffu, pg1, o);
            }
            if (glan == 0) {
                gz[0] = sigf(li_sh[0][t] + pg0 + blg);
                gz[1] = sigf(li_sh[1][t] + pg1 + blg);
                gz[2] = z_sh[0][t];
                gz[3] = z_sh[1][t];
            }
        }
        __syncthreads();
        if (tid < 100) {
            float m0 = ph[0][0][tid] + ph[1][0][tid] + ph[2][0][tid] + ph[3][0][tid];
            float m1 = ph[0][1][tid] + ph[1][1][tid] + ph[2][1][tid] + ph[3][1][tid];
            float g0 = gz[0], g1 = gz[1], zz0 = gz[2], zz1 = gz[3];
            float s0 = stsh[0][tid], s1 = stsh[1][tid];
            float ns0 = tanh_fast(tv0 + g0 * m0 + btsr);
            float ns1 = tanh_fast(tv1 + g1 * m1 + btsr);
            stsh[0][tid] = (1.f - zz0) * s0 + zz0 * ns0;
            stsh[1][tid] = (1.f - zz1) * s1 + zz1 * ns1;
            tv0 = tn0; tv1 = tn1;
        }
        __syncthreads();
    }

    if (tid < 100) {
        g_state[b0 * Hz + tid]       = stsh[0][tid];
        g_state[(b0 + 1) * Hz + tid] = stsh[1][tid];
    }
}

// ---------------- K7: output projection ----------------
__global__ void __launch_bounds__(256) out_kernel(const float* __restrict__ Wout,
                                                  const float* __restrict__ bout,
                                                  float* __restrict__ out) {
    int idx = blockIdx.x * 256 + threadIdx.x;
    if (idx >= Bz * NCz) return;
    int b = idx / NCz, c = idx % NCz;
    float acc = bout[c];
    const float* s = g_state + b * Hz;
    const float* wr = Wout + c * Hz;
    #pragma unroll
    for (int k = 0; k < Hz; k++) acc += s[k] * wr[k];
    out[idx] = acc;
}

// ---------------- launch ----------------
extern "C" void kernel_launch(void* const* d_in, const int* in_sizes, int n_in,
                              void* d_out, int out_size) {
    const int*   txt   = (const int*)d_in[0];
    const int*   lens  = (const int*)d_in[1];
    const float* emb   = (const float*)d_in[2];
    const float* W_ih  = (const float*)d_in[3];
    const float* W_hh  = (const float*)d_in[4];
    const float* b_ih  = (const float*)d_in[5];
    const float* b_hh  = (const float*)d_in[6];
    const float* W_lgr = (const float*)d_in[7];
    const float* b_lgr = (const float*)d_in[8];
    const float* W_ts  = (const float*)d_in[9];
    const float* b_ts  = (const float*)d_in[10];
    const float* W_ti  = (const float*)d_in[11];
    const float* b_ti  = (const float*)d_in[12];
    const float* W_out = (const float*)d_in[13];
    const float* b_out = (const float*)d_in[14];
    float* out = (float*)d_out;

    float* xp  = nullptr; cudaGetSymbolAddress((void**)&xp,  g_xp);
    float* rnn = nullptr; cudaGetSymbolAddress((void**)&rnn, g_rnn);
    float* ti  = nullptr; cudaGetSymbolAddress((void**)&ti,  g_ti);

    scale_kernel<<<BT / 8, 256>>>(txt, emb);

    {
        constexpr int SMEM = (64 + 160) * 204 * 4;
        cudaFuncSetAttribute((const void*)mma_gemm_kernel<200, 200, 204, 160, 40, true>,
                             cudaFuncAttributeMaxDynamicSharedMemorySize, SMEM);
        dim3 grid(BT / 64, 2);
        mma_gemm_kernel<200, 200, 204, 160, 40, true><<<grid, 256, SMEM>>>(
            nullptr, txt, emb, W_ih, b_ih, xp, 300);
    }

    // dummy: ncu capture slot (4th of our launches) — next interesting kernel
    dummy_kernel<<<1, 32>>>();

    gru_kernel<<<Bz / 2, 640>>>(W_hh, b_hh);

    zli_kernel<<<BT / 8, 256>>>(W_lgr, lens);

    {
        constexpr int SMEM = (64 + 128) * 108 * 4;
        cudaFuncSetAttribute((const void*)mma_gemm_kernel<100, 104, 108, 128, 32, false>,
                             cudaFuncAttributeMaxDynamicSharedMemorySize, SMEM);
        dim3 grid(BT / 64, 1);
        mma_gemm_kernel<100, 104, 108, 128, 32, false><<<grid, 256, SMEM>>>(
            rnn, nullptr, nullptr, W_ti, b_ti, ti, 100);
    }

    rec_kernel<<<Bz / 2, 448>>>(W_ts, b_ts, W_lgr, b_lgr);

    out_kernel<<<(Bz * NCz + 255) / 256, 256>>>(W_out, b_out, out);
}

// round 15
// speedup vs baseline: 1.0510x; 1.0510x over previous
#include <cuda_runtime.h>
#include <cstdint>

#define Bz   256
#define Tz   512
#define Ez   200
#define Hz   100
#define NCz  5
#define BT   131072      // B*T

typedef unsigned long long ull;

// ---------------- scratch ----------------
__device__ float g_scale[BT];
__device__ float g_xp[(size_t)BT * 300];   // 157 MB
__device__ float g_rnn[(size_t)BT * 100];  // 52 MB
__device__ float g_ti[(size_t)BT * 100];   // 52 MB
__device__ float g_z[BT];
__device__ float g_li[BT];
__device__ float g_state[Bz * Hz];

// ---------------- helpers ----------------
__device__ __forceinline__ float sigf(float x) {
    return 1.0f / (1.0f + __expf(-x));
}
__device__ __forceinline__ float tanh_fast(float x) {
    float t = __expf(-2.0f * fabsf(x));
    float r = (1.0f - t) / (1.0f + t);
    return copysignf(r, x);
}
__device__ __forceinline__ float to_tf32(float x) {
    uint32_t u;
    asm("cvt.rna.tf32.f32 %0, %1;" : "=r"(u) : "f"(x));
    return __uint_as_float(u);
}
__device__ __forceinline__ void fma2(ull& d, ull a, ull b) {
    asm("fma.rn.f32x2 %0, %1, %2, %0;" : "+l"(d) : "l"(a), "l"(b));
}
__device__ __forceinline__ float upksum(ull v) {
    float lo, hi;
    asm("mov.b64 {%0,%1}, %2;" : "=f"(lo), "=f"(hi) : "l"(v));
    return lo + hi;
}
__device__ __forceinline__ void named_bar(int id, int cnt) {
    asm volatile("bar.sync %0, %1;" :: "r"(id), "r"(cnt) : "memory");
}

// ---------------- K1: per-row embedding norm scale ----------------
__global__ void __launch_bounds__(256) scale_kernel(const int* __restrict__ txt,
                                                    const float* __restrict__ emb) {
    int warp = (blockIdx.x * 256 + threadIdx.x) >> 5;
    int lane = threadIdx.x & 31;
    if (warp >= BT) return;
    int tok = txt[warp];
    const float* row = emb + (size_t)tok * Ez;
    float ss = 0.f;
    for (int k = lane; k < Ez; k += 32) { float v = row[k]; ss += v * v; }
    #pragma unroll
    for (int o = 16; o > 0; o >>= 1) ss += __shfl_xor_sync(0xffffffffu, ss, o);
    if (lane == 0) {
        float n = sqrtf(ss);
        g_scale[warp] = (n > 1.0f) ? 1.0f / (n + 1e-7f) : 1.0f;
    }
}

// ---------------- dummy (keeps ncu capture slot on gru_kernel) ----------------
__global__ void dummy_kernel() {}

// ---------------- K2/K5: tf32 MMA GEMM ----------------
template <int KDIM, int KCEIL, int KSTR, int TN, int WNc, bool GATHER>
__global__ void __launch_bounds__(256) mma_gemm_kernel(
    const float* __restrict__ Ain,
    const int* __restrict__ txt,
    const float* __restrict__ emb,
    const float* __restrict__ W,
    const float* __restrict__ bias,
    float* __restrict__ C,
    int NV)
{
    extern __shared__ float sm[];
    float* As = sm;
    float* Bs = sm + 64 * KSTR;
    __shared__ int   s_tok[64];
    __shared__ float s_scl[64];

    const int tid   = threadIdx.x;
    const int rbase = blockIdx.x * 64;
    const int nbase = blockIdx.y * TN;

    if (GATHER) {
        if (tid < 64) {
            int r = rbase + tid;
            s_tok[tid] = txt[r];
            s_scl[tid] = g_scale[r];
        }
        __syncthreads();
    }

    const int K4 = KCEIL / 4;
    for (int e = tid; e < 64 * K4; e += 256) {
        int row = e / K4, k4 = e % K4;
        float4 v = make_float4(0.f, 0.f, 0.f, 0.f);
        if (4 * k4 + 3 < KDIM) {
            if (GATHER) {
                const float4* p = (const float4*)(emb + (size_t)s_tok[row] * KDIM) + k4;
                v = *p;
                float s = s_scl[row];
                v.x *= s; v.y *= s; v.z *= s; v.w *= s;
            } else {
                const float4* p = (const float4*)(Ain + (size_t)(rbase + row) * KDIM) + k4;
                v = *p;
            }
        }
        float4 o = make_float4(to_tf32(v.x), to_tf32(v.y), to_tf32(v.z), to_tf32(v.w));
        *(float4*)(As + row * KSTR + 4 * k4) = o;
    }
    for (int e = tid; e < TN * K4; e += 256) {
        int n = e / K4, k4 = e % K4;
        int ng = nbase + n;
        float4 v = make_float4(0.f, 0.f, 0.f, 0.f);
        if (ng < NV && 4 * k4 + 3 < KDIM) {
            const float4* p = (const float4*)(W + (size_t)ng * KDIM) + k4;
            v = *p;
        }
        float4 o = make_float4(to_tf32(v.x), to_tf32(v.y), to_tf32(v.z), to_tf32(v.w));
        *(float4*)(Bs + n * KSTR + 4 * k4) = o;
    }
    __syncthreads();

    const int wid  = tid >> 5;
    const int lane = tid & 31;
    const int g    = lane >> 2;
    const int tg   = lane & 3;
    const int mwarp = wid & 1;
    const int nwarp = wid >> 1;
    const int NF = WNc / 8;

    float c[2][NF][4];
    #pragma unroll
    for (int mt = 0; mt < 2; mt++)
        #pragma unroll
        for (int nf = 0; nf < NF; nf++)
            #pragma unroll
            for (int i = 0; i < 4; i++) c[mt][nf][i] = 0.f;

    const float* Aw = As + (mwarp * 32) * KSTR;
    const float* Bw = Bs + (nwarp * WNc) * KSTR;

    #pragma unroll 1
    for (int k8 = 0; k8 < KCEIL / 8; k8++) {
        int k0 = k8 * 8;
        uint32_t a[2][4], b[NF][2];
        #pragma unroll
        for (int mt = 0; mt < 2; mt++) {
            const float* ap = Aw + (mt * 16 + g) * KSTR + k0 + tg;
            a[mt][0] = __float_as_uint(ap[0]);
            a[mt][1] = __float_as_uint(ap[8 * KSTR]);
            a[mt][2] = __float_as_uint(ap[4]);
            a[mt][3] = __float_as_uint(ap[8 * KSTR + 4]);
        }
        #pragma unroll
        for (int nf = 0; nf < NF; nf++) {
            const float* bp = Bw + (nf * 8 + g) * KSTR + k0 + tg;
            b[nf][0] = __float_as_uint(bp[0]);
            b[nf][1] = __float_as_uint(bp[4]);
        }
        #pragma unroll
        for (int mt = 0; mt < 2; mt++)
            #pragma unroll
            for (int nf = 0; nf < NF; nf++) {
                asm volatile(
                    "mma.sync.aligned.m16n8k8.row.col.f32.tf32.tf32.f32 "
                    "{%0,%1,%2,%3}, {%4,%5,%6,%7}, {%8,%9}, {%0,%1,%2,%3};"
                    : "+f"(c[mt][nf][0]), "+f"(c[mt][nf][1]),
                      "+f"(c[mt][nf][2]), "+f"(c[mt][nf][3])
                    : "r"(a[mt][0]), "r"(a[mt][1]), "r"(a[mt][2]), "r"(a[mt][3]),
                      "r"(b[nf][0]), "r"(b[nf][1]));
            }
    }

    #pragma unroll
    for (int mt = 0; mt < 2; mt++) {
        int row = rbase + mwarp * 32 + mt * 16 + g;
        #pragma unroll
        for (int nf = 0; nf < NF; nf++) {
            int col = nbase + nwarp * WNc + nf * 8 + 2 * tg;
            if (col < NV) {
                float b0 = bias[col], b1 = bias[col + 1];
                float2 v0 = make_float2(c[mt][nf][0] + b0, c[mt][nf][1] + b1);
                float2 v1 = make_float2(c[mt][nf][2] + b0, c[mt][nf][3] + b1);
                *(float2*)(C + (size_t)row * NV + col) = v0;
                *(float2*)(C + (size_t)(row + 8) * NV + col) = v1;
            }
        }
    }
}

// ============================================================================
// K3: GRU scan v6 — warp-granular k-split + PACKED partial exchange.
// 128 blocks (2 batches), 640 threads:
//   warps 0-9  : half 0 (k 0..49)  of row = tid       (>=300 dummy)
//   warps 10-19: half 1 (k 50..99) of row = tid - 320 (>=300 dummy)
// ph layout [half][row][{b0,b1}]: GEMV threads write ONE coalesced STS.64;
// updaters read 6 LDS.64. Halves STS-in-flight at the barrier vs v5.
// ============================================================================
__global__ void __launch_bounds__(640, 1) gru_kernel(const float* __restrict__ Whh,
                                                     const float* __restrict__ bhh) {
    __shared__ __align__(16) float hsh[2][104];     // [batch][k]
    __shared__ __align__(16) float ph[2][304][2];   // [half][row][{b0,b1}]
    const int tid = threadIdx.x;
    const int b0 = blockIdx.x * 2;
    const float* x0 = g_xp + (size_t)b0 * Tz * 300;
    const float* x1 = x0 + (size_t)Tz * 300;

    const int half = (tid >= 320) ? 1 : 0;
    const int row  = tid - half * 320;              // 0..319
    const int rcl  = (row < 300) ? row : 299;
    const bool act = (row < 300);

    if (tid < 104) { hsh[0][tid] = 0.f; hsh[1][tid] = 0.f; }

    ull ws, wv[24];
    {
        const ull* p = (const ull*)(Whh + rcl * 100 + half * 50);
        if (half == 0) {
            ws = p[24];
            #pragma unroll
            for (int q = 0; q < 24; q++) wv[q] = p[q];
        } else {
            ws = p[0];
            #pragma unroll
            for (int q = 0; q < 24; q++) wv[q] = p[1 + q];
        }
    }
    const int sidx = half ? 25 : 24;
    const int vec0 = half ? 26 : 0;
    float bias_r = (half == 0) ? bhh[rcl] : 0.f;

    float xr0 = 0.f, xz0 = 0.f, xn0 = 0.f, xr1 = 0.f, xz1 = 0.f, xn1 = 0.f;
    if (tid < 100) {
        xr0 = x0[tid]; xz0 = x0[100 + tid]; xn0 = x0[200 + tid];
        xr1 = x1[tid]; xz1 = x1[100 + tid]; xn1 = x1[200 + tid];
    }
    __syncthreads();

    for (int t = 0; t < Tz; t++) {
        float nr0 = 0.f, nz0 = 0.f, nn0 = 0.f, nr1 = 0.f, nz1 = 0.f, nn1 = 0.f;
        if (tid < 100 && t + 1 < Tz) {
            const float* p0 = x0 + (size_t)(t + 1) * 300;
            const float* p1 = x1 + (size_t)(t + 1) * 300;
            nr0 = p0[tid]; nz0 = p0[100 + tid]; nn0 = p0[200 + tid];
            nr1 = p1[tid]; nz1 = p1[100 + tid]; nn1 = p1[200 + tid];
        }
        {
            const ull* B0 = (const ull*)&hsh[0][0];
            const ull* B1 = B0 + 52;
            ull a0 = 0ull, d0 = 0ull, a1 = 0ull, d1 = 0ull;
            fma2(a0, ws, B0[sidx]);
            fma2(a1, ws, B1[sidx]);
            const ulonglong2* V0 = (const ulonglong2*)(B0 + vec0);
            const ulonglong2* V1 = (const ulonglong2*)(B1 + vec0);
            #pragma unroll
            for (int q = 0; q < 12; q++) {
                ulonglong2 h0 = V0[q], h1 = V1[q];
                fma2(a0, wv[2 * q],     h0.x);
                fma2(d0, wv[2 * q + 1], h0.y);
                fma2(a1, wv[2 * q],     h1.x);
                fma2(d1, wv[2 * q + 1], h1.y);
            }
            if (act) {
                float o0 = upksum(a0) + upksum(d0) + bias_r;
                float o1 = upksum(a1) + upksum(d1) + bias_r;
                *(float2*)&ph[half][row][0] = make_float2(o0, o1);
            }
        }
        __syncthreads();
        if (tid < 100) {
            int j = tid;
            float2 r0p = *(float2*)&ph[0][j][0];
            float2 r1p = *(float2*)&ph[1][j][0];
            float2 z0p = *(float2*)&ph[0][100 + j][0];
            float2 z1p = *(float2*)&ph[1][100 + j][0];
            float2 n0p = *(float2*)&ph[0][200 + j][0];
            float2 n1p = *(float2*)&ph[1][200 + j][0];
            float hr0 = r0p.x + r1p.x, hr1 = r0p.y + r1p.y;
            float hz0 = z0p.x + z1p.x, hz1 = z0p.y + z1p.y;
            float hn0 = n0p.x + n1p.x, hn1 = n0p.y + n1p.y;
            float ho0 = hsh[0][j], ho1 = hsh[1][j];
            float r0 = sigf(xr0 + hr0), r1 = sigf(xr1 + hr1);
            float z0 = sigf(xz0 + hz0), z1 = sigf(xz1 + hz1);
            float n0 = tanh_fast(xn0 + r0 * hn0);
            float n1 = tanh_fast(xn1 + r1 * hn1);
            float hx = (1.f - z0) * n0 + z0 * ho0;
            float hy = (1.f - z1) * n1 + z1 * ho1;
            hsh[0][j] = hx;
            hsh[1][j] = hy;
            g_rnn[((size_t)b0 * Tz + t) * Hz + j]       = hx;
            g_rnn[((size_t)(b0 + 1) * Tz + t) * Hz + j] = hy;
            xr0 = nr0; xz0 = nz0; xn0 = nn0;
            xr1 = nr1; xz1 = nz1; xn1 = nn1;
        }
        __syncthreads();
    }
}

// ---------------- K4: per-(b,t) z (attention gate) and lgr_in ----------------
__global__ void __launch_bounds__(256) zli_kernel(const float* __restrict__ Wlgr,
                                                  const int* __restrict__ lens) {
    int warp = (blockIdx.x * 256 + threadIdx.x) >> 5;
    int lane = threadIdx.x & 31;
    if (warp >= BT) return;
    int b = warp >> 9;
    int t = warp & (Tz - 1);
    const float* r = g_rnn + (size_t)warp * Hz;
    float s1 = 0.f, s2 = 0.f, s3 = 0.f;
    for (int k = lane; k < Hz; k += 32) {
        float v = r[k];
        s1 += v;
        s2 += v * v;
        s3 += v * Wlgr[k];
    }
    #pragma unroll
    for (int o = 16; o > 0; o >>= 1) {
        s1 += __shfl_xor_sync(0xffffffffu, s1, o);
        s2 += __shfl_xor_sync(0xffffffffu, s2, o);
        s3 += __shfl_xor_sync(0xffffffffu, s3, o);
    }
    if (lane == 0) {
        float nrm = sqrtf(s2);
        float att = 0.001f * s1 / fmaxf(nrm, 1e-12f);
        float zv = (t < lens[b] && att > 0.f) ? att : 0.f;
        g_z[warp]  = zv;
        g_li[warp] = s3;
    }
}

// ============================================================================
// K6: second recurrence v3 (R13 best) — two independent batch groups with
// NAMED barriers. 128 blocks, 320 threads = 2 groups x 160 (warps 0-4 / 5-9).
// ============================================================================
__global__ void __launch_bounds__(320, 1) rec_kernel(const float* __restrict__ Wts,
                                                     const float* __restrict__ bts,
                                                     const float* __restrict__ Wlgr,
                                                     const float* __restrict__ blgr) {
    __shared__ __align__(16) float stsh[2][104];    // [group][k]
    __shared__ float li_sh[2][Tz];
    __shared__ float z_sh[2][Tz];
    __shared__ float gz[2][2];                      // [group][{gate,z}]
    const int tid = threadIdx.x;
    const int g  = (tid >= 160) ? 1 : 0;
    const int lt = tid - g * 160;
    const int b0 = blockIdx.x * 2;
    const int bb = b0 + g;

    for (int i = tid; i < Tz; i += 320) {
        li_sh[0][i] = g_li[(size_t)b0 * Tz + i];
        li_sh[1][i] = g_li[(size_t)(b0 + 1) * Tz + i];
        z_sh[0][i]  = g_z[(size_t)b0 * Tz + i];
        z_sh[1][i]  = g_z[(size_t)(b0 + 1) * Tz + i];
    }
    if (tid < 104) { stsh[0][tid] = 0.f; stsh[1][tid] = 0.f; }

    ull w[50];
    float btsr = 0.f, tv = 0.f, tn = 0.f;
    const float* tb = nullptr;
    if (lt < 100) {
        const ull* wp = (const ull*)(Wts + lt * 100);
        #pragma unroll
        for (int q = 0; q < 50; q++) w[q] = wp[q];
        btsr = bts[lt];
        tb = g_ti + (size_t)bb * Tz * Hz + lt;
        tv = tb[0];
        tn = tb[Hz];
    }
    float wl4[4] = {0.f, 0.f, 0.f, 0.f};
    float blg = 0.f;
    const int glan = lt - 128;
    if (lt >= 128) {
        #pragma unroll
        for (int i = 0; i < 4; i++) {
            int k = glan + 32 * i;
            wl4[i] = (k < 100) ? Wlgr[100 + k] : 0.f;
        }
        blg = blgr[0];
    }
    __syncthreads();

    for (int t = 0; t < Tz; t++) {
        float m = 0.f, tn2 = 0.f;
        if (lt < 100) {
            if (t + 2 < Tz) tn2 = tb[(size_t)(t + 2) * Hz];
            ull aA = 0ull, aB = 0ull;
            const ulonglong2* S = (const ulonglong2*)&stsh[g][0];
            #pragma unroll
            for (int v = 0; v < 25; v++) {
                ulonglong2 s = S[v];
                fma2(aA, w[2 * v],     s.x);
                fma2(aB, w[2 * v + 1], s.y);
            }
            m = upksum(aA) + upksum(aB);
        } else if (lt >= 128) {
            float pg = 0.f;
            #pragma unroll
            for (int i = 0; i < 4; i++) {
                int k = glan + 32 * i;
                if (k < 100) pg += wl4[i] * stsh[g][k];
            }
            #pragma unroll
            for (int o = 16; o > 0; o >>= 1)
                pg += __shfl_xor_sync(0xffffffffu, pg, o);
            if (glan == 0) {
                gz[g][0] = sigf(li_sh[g][t] + pg + blg);
                gz[g][1] = z_sh[g][t];
            }
        }
        named_bar(1 + g, 160);
        if (lt < 100) {
            float gg = gz[g][0], zz = gz[g][1];
            float s = stsh[g][lt];
            float ns = tanh_fast(tv + gg * m + btsr);
            stsh[g][lt] = (1.f - zz) * s + zz * ns;
            tv = tn; tn = tn2;
        }
        named_bar(1 + g, 160);
    }

    if (lt < 100)
        g_state[bb * Hz + lt] = stsh[g][lt];
}

// ---------------- K7: output projection ----------------
__global__ void __launch_bounds__(256) out_kernel(const float* __restrict__ Wout,
                                                  const float* __restrict__ bout,
                                                  float* __restrict__ out) {
    int idx = blockIdx.x * 256 + threadIdx.x;
    if (idx >= Bz * NCz) return;
    int b = idx / NCz, c = idx % NCz;
    float acc = bout[c];
    const float* s = g_state + b * Hz;
    const float* wr = Wout + c * Hz;
    #pragma unroll
    for (int k = 0; k < Hz; k++) acc += s[k] * wr[k];
    out[idx] = acc;
}

// ---------------- launch ----------------
extern "C" void kernel_launch(void* const* d_in, const int* in_sizes, int n_in,
                              void* d_out, int out_size) {
    const int*   txt   = (const int*)d_in[0];
    const int*   lens  = (const int*)d_in[1];
    const float* emb   = (const float*)d_in[2];
    const float* W_ih  = (const float*)d_in[3];
    const float* W_hh  = (const float*)d_in[4];
    const float* b_ih  = (const float*)d_in[5];
    const float* b_hh  = (const float*)d_in[6];
    const float* W_lgr = (const float*)d_in[7];
    const float* b_lgr = (const float*)d_in[8];
    const float* W_ts  = (const float*)d_in[9];
    const float* b_ts  = (const float*)d_in[10];
    const float* W_ti  = (const float*)d_in[11];
    const float* b_ti  = (const float*)d_in[12];
    const float* W_out = (const float*)d_in[13];
    const float* b_out = (const float*)d_in[14];
    float* out = (float*)d_out;

    float* xp  = nullptr; cudaGetSymbolAddress((void**)&xp,  g_xp);
    float* rnn = nullptr; cudaGetSymbolAddress((void**)&rnn, g_rnn);
    float* ti  = nullptr; cudaGetSymbolAddress((void**)&ti,  g_ti);

    scale_kernel<<<BT / 8, 256>>>(txt, emb);

    {
        constexpr int SMEM = (64 + 160) * 204 * 4;
        cudaFuncSetAttribute((const void*)mma_gemm_kernel<200, 200, 204, 160, 40, true>,
                             cudaFuncAttributeMaxDynamicSharedMemorySize, SMEM);
        dim3 grid(BT / 64, 2);
        mma_gemm_kernel<200, 200, 204, 160, 40, true><<<grid, 256, SMEM>>>(
            nullptr, txt, emb, W_ih, b_ih, xp, 300);
    }

    // dummy: ncu capture slot lands on gru_kernel
    dummy_kernel<<<1, 32>>>();

    gru_kernel<<<Bz / 2, 640>>>(W_hh, b_hh);

    zli_kernel<<<BT / 8, 256>>>(W_lgr, lens);

    {
        constexpr int SMEM = (64 + 128) * 108 * 4;
        cudaFuncSetAttribute((const void*)mma_gemm_kernel<100, 104, 108, 128, 32, false>,
                             cudaFuncAttributeMaxDynamicSharedMemorySize, SMEM);
        dim3 grid(BT / 64, 1);
        mma_gemm_kernel<100, 104, 108, 128, 32, false><<<grid, 256, SMEM>>>(
            rnn, nullptr, nullptr, W_ti, b_ti, ti, 100);
    }

    rec_kernel<<<Bz / 2, 320>>>(W_ts, b_ts, W_lgr, b_lgr);

    out_kernel<<<(Bz * NCz + 255) / 256, 256>>>(W_out, b_out, out);
}

// round 16
// speedup vs baseline: 1.0980x; 1.0447x over previous
#include <cuda_runtime.h>
#include <cstdint>

#define Bz   256
#define Tz   512
#define Ez   200
#define Hz   100
#define NCz  5
#define BT   131072      // B*T

typedef unsigned long long ull;

// ---------------- scratch ----------------
__device__ float g_scale[BT];
__device__ float g_xp[(size_t)BT * 300];   // 157 MB
__device__ float g_rnn[(size_t)BT * 100];  // 52 MB
__device__ float g_ti[(size_t)BT * 100];   // 52 MB
__device__ float g_z[BT];
__device__ float g_li[BT];
__device__ float g_state[Bz * Hz];

// ---------------- helpers ----------------
__device__ __forceinline__ float sigf(float x) {
    return 1.0f / (1.0f + __expf(-x));
}
__device__ __forceinline__ float tanh_fast(float x) {
    float t = __expf(-2.0f * fabsf(x));
    float r = (1.0f - t) / (1.0f + t);
    return copysignf(r, x);
}
__device__ __forceinline__ float to_tf32(float x) {
    uint32_t u;
    asm("cvt.rna.tf32.f32 %0, %1;" : "=r"(u) : "f"(x));
    return __uint_as_float(u);
}
__device__ __forceinline__ void fma2(ull& d, ull a, ull b) {
    asm("fma.rn.f32x2 %0, %1, %2, %0;" : "+l"(d) : "l"(a), "l"(b));
}
__device__ __forceinline__ float upksum(ull v) {
    float lo, hi;
    asm("mov.b64 {%0,%1}, %2;" : "=f"(lo), "=f"(hi) : "l"(v));
    return lo + hi;
}
__device__ __forceinline__ void named_bar(int id, int cnt) {
    asm volatile("bar.sync %0, %1;" :: "r"(id), "r"(cnt) : "memory");
}

// ---------------- K1: per-row embedding norm scale ----------------
__global__ void __launch_bounds__(256) scale_kernel(const int* __restrict__ txt,
                                                    const float* __restrict__ emb) {
    int warp = (blockIdx.x * 256 + threadIdx.x) >> 5;
    int lane = threadIdx.x & 31;
    if (warp >= BT) return;
    int tok = txt[warp];
    const float* row = emb + (size_t)tok * Ez;
    float ss = 0.f;
    for (int k = lane; k < Ez; k += 32) { float v = row[k]; ss += v * v; }
    #pragma unroll
    for (int o = 16; o > 0; o >>= 1) ss += __shfl_xor_sync(0xffffffffu, ss, o);
    if (lane == 0) {
        float n = sqrtf(ss);
        g_scale[warp] = (n > 1.0f) ? 1.0f / (n + 1e-7f) : 1.0f;
    }
}

// ---------------- dummy (shifts ncu capture slot) ----------------
__global__ void dummy_kernel() {}

// ---------------- K2/K5: tf32 MMA GEMM with K-panels ----------------
// NPAN panels of PANK floats each. Accumulators persist in registers across
// panels; smem holds one panel (KSTR floats/row), so K2 fits 2 CTAs/SM.
template <int KDIM, int PANK, int NPAN, int KCEIL, int KSTR, int TN, int WNc, bool GATHER>
__global__ void __launch_bounds__(256) mma_gemm_kernel(
    const float* __restrict__ Ain,
    const int* __restrict__ txt,
    const float* __restrict__ emb,
    const float* __restrict__ W,
    const float* __restrict__ bias,
    float* __restrict__ C,
    int NV)
{
    extern __shared__ float sm[];
    float* As = sm;
    float* Bs = sm + 64 * KSTR;
    __shared__ int   s_tok[64];
    __shared__ float s_scl[64];

    const int tid   = threadIdx.x;
    const int rbase = blockIdx.x * 64;
    const int nbase = blockIdx.y * TN;

    if (GATHER) {
        if (tid < 64) {
            int r = rbase + tid;
            s_tok[tid] = txt[r];
            s_scl[tid] = g_scale[r];
        }
        __syncthreads();
    }

    const int wid  = tid >> 5;
    const int lane = tid & 31;
    const int g    = lane >> 2;
    const int tg   = lane & 3;
    const int mwarp = wid & 1;
    const int nwarp = wid >> 1;
    const int NF = WNc / 8;

    float c[2][NF][4];
    #pragma unroll
    for (int mt = 0; mt < 2; mt++)
        #pragma unroll
        for (int nf = 0; nf < NF; nf++)
            #pragma unroll
            for (int i = 0; i < 4; i++) c[mt][nf][i] = 0.f;

    const int K4 = KCEIL / 4;

    #pragma unroll 1
    for (int kp = 0; kp < NPAN; kp++) {
        const int kbase = kp * PANK;
        const int rem   = KDIM - kbase;            // floats valid in this panel
        // ---- fill A panel ----
        for (int e = tid; e < 64 * K4; e += 256) {
            int row = e / K4, k4 = e % K4;
            float4 v = make_float4(0.f, 0.f, 0.f, 0.f);
            if (4 * k4 + 3 < rem) {
                if (GATHER) {
                    const float4* p = (const float4*)(emb + (size_t)s_tok[row] * KDIM + kbase) + k4;
                    v = *p;
                    float s = s_scl[row];
                    v.x *= s; v.y *= s; v.z *= s; v.w *= s;
                } else {
                    const float4* p = (const float4*)(Ain + (size_t)(rbase + row) * KDIM + kbase) + k4;
                    v = *p;
                }
            }
            float4 o = make_float4(to_tf32(v.x), to_tf32(v.y), to_tf32(v.z), to_tf32(v.w));
            *(float4*)(As + row * KSTR + 4 * k4) = o;
        }
        // ---- fill B panel ----
        for (int e = tid; e < TN * K4; e += 256) {
            int n = e / K4, k4 = e % K4;
            int ng = nbase + n;
            float4 v = make_float4(0.f, 0.f, 0.f, 0.f);
            if (ng < NV && 4 * k4 + 3 < rem) {
                const float4* p = (const float4*)(W + (size_t)ng * KDIM + kbase) + k4;
                v = *p;
            }
            float4 o = make_float4(to_tf32(v.x), to_tf32(v.y), to_tf32(v.z), to_tf32(v.w));
            *(float4*)(Bs + n * KSTR + 4 * k4) = o;
        }
        __syncthreads();

        const float* Aw = As + (mwarp * 32) * KSTR;
        const float* Bw = Bs + (nwarp * WNc) * KSTR;

        #pragma unroll 1
        for (int k8 = 0; k8 < KCEIL / 8; k8++) {
            int k0 = k8 * 8;
            uint32_t a[2][4], b[NF][2];
            #pragma unroll
            for (int mt = 0; mt < 2; mt++) {
                const float* ap = Aw + (mt * 16 + g) * KSTR + k0 + tg;
                a[mt][0] = __float_as_uint(ap[0]);
                a[mt][1] = __float_as_uint(ap[8 * KSTR]);
                a[mt][2] = __float_as_uint(ap[4]);
                a[mt][3] = __float_as_uint(ap[8 * KSTR + 4]);
            }
            #pragma unroll
            for (int nf = 0; nf < NF; nf++) {
                const float* bp = Bw + (nf * 8 + g) * KSTR + k0 + tg;
                b[nf][0] = __float_as_uint(bp[0]);
                b[nf][1] = __float_as_uint(bp[4]);
            }
            #pragma unroll
            for (int mt = 0; mt < 2; mt++)
                #pragma unroll
                for (int nf = 0; nf < NF; nf++) {
                    asm volatile(
                        "mma.sync.aligned.m16n8k8.row.col.f32.tf32.tf32.f32 "
                        "{%0,%1,%2,%3}, {%4,%5,%6,%7}, {%8,%9}, {%0,%1,%2,%3};"
                        : "+f"(c[mt][nf][0]), "+f"(c[mt][nf][1]),
                          "+f"(c[mt][nf][2]), "+f"(c[mt][nf][3])
                        : "r"(a[mt][0]), "r"(a[mt][1]), "r"(a[mt][2]), "r"(a[mt][3]),
                          "r"(b[nf][0]), "r"(b[nf][1]));
                }
        }
        __syncthreads();
    }

    #pragma unroll
    for (int mt = 0; mt < 2; mt++) {
        int row = rbase + mwarp * 32 + mt * 16 + g;
        #pragma unroll
        for (int nf = 0; nf < NF; nf++) {
            int col = nbase + nwarp * WNc + nf * 8 + 2 * tg;
            if (col < NV) {
                float b0 = bias[col], b1 = bias[col + 1];
                float2 v0 = make_float2(c[mt][nf][0] + b0, c[mt][nf][1] + b1);
                float2 v1 = make_float2(c[mt][nf][2] + b0, c[mt][nf][3] + b1);
                *(float2*)(C + (size_t)row * NV + col) = v0;
                *(float2*)(C + (size_t)(row + 8) * NV + col) = v1;
            }
        }
    }
}

// ============================================================================
// K3: GRU scan v6 (R15 best) — warp-granular k-split + packed ph exchange.
// ============================================================================
__global__ void __launch_bounds__(640, 1) gru_kernel(const float* __restrict__ Whh,
                                                     const float* __restrict__ bhh) {
    __shared__ __align__(16) float hsh[2][104];     // [batch][k]
    __shared__ __align__(16) float ph[2][304][2];   // [half][row][{b0,b1}]
    const int tid = threadIdx.x;
    const int b0 = blockIdx.x * 2;
    const float* x0 = g_xp + (size_t)b0 * Tz * 300;
    const float* x1 = x0 + (size_t)Tz * 300;

    const int half = (tid >= 320) ? 1 : 0;
    const int row  = tid - half * 320;              // 0..319
    const int rcl  = (row < 300) ? row : 299;
    const bool act = (row < 300);

    if (tid < 104) { hsh[0][tid] = 0.f; hsh[1][tid] = 0.f; }

    ull ws, wv[24];
    {
        const ull* p = (const ull*)(Whh + rcl * 100 + half * 50);
        if (half == 0) {
            ws = p[24];
            #pragma unroll
            for (int q = 0; q < 24; q++) wv[q] = p[q];
        } else {
            ws = p[0];
            #pragma unroll
            for (int q = 0; q < 24; q++) wv[q] = p[1 + q];
        }
    }
    const int sidx = half ? 25 : 24;
    const int vec0 = half ? 26 : 0;
    float bias_r = (half == 0) ? bhh[rcl] : 0.f;

    float xr0 = 0.f, xz0 = 0.f, xn0 = 0.f, xr1 = 0.f, xz1 = 0.f, xn1 = 0.f;
    if (tid < 100) {
        xr0 = x0[tid]; xz0 = x0[100 + tid]; xn0 = x0[200 + tid];
        xr1 = x1[tid]; xz1 = x1[100 + tid]; xn1 = x1[200 + tid];
    }
    __syncthreads();

    for (int t = 0; t < Tz; t++) {
        float nr0 = 0.f, nz0 = 0.f, nn0 = 0.f, nr1 = 0.f, nz1 = 0.f, nn1 = 0.f;
        if (tid < 100 && t + 1 < Tz) {
            const float* p0 = x0 + (size_t)(t + 1) * 300;
            const float* p1 = x1 + (size_t)(t + 1) * 300;
            nr0 = p0[tid]; nz0 = p0[100 + tid]; nn0 = p0[200 + tid];
            nr1 = p1[tid]; nz1 = p1[100 + tid]; nn1 = p1[200 + tid];
        }
        {
            const ull* B0 = (const ull*)&hsh[0][0];
            const ull* B1 = B0 + 52;
            ull a0 = 0ull, d0 = 0ull, a1 = 0ull, d1 = 0ull;
            fma2(a0, ws, B0[sidx]);
            fma2(a1, ws, B1[sidx]);
            const ulonglong2* V0 = (const ulonglong2*)(B0 + vec0);
            const ulonglong2* V1 = (const ulonglong2*)(B1 + vec0);
            #pragma unroll
            for (int q = 0; q < 12; q++) {
                ulonglong2 h0 = V0[q], h1 = V1[q];
                fma2(a0, wv[2 * q],     h0.x);
                fma2(d0, wv[2 * q + 1], h0.y);
                fma2(a1, wv[2 * q],     h1.x);
                fma2(d1, wv[2 * q + 1], h1.y);
            }
            if (act) {
                float o0 = upksum(a0) + upksum(d0) + bias_r;
                float o1 = upksum(a1) + upksum(d1) + bias_r;
                *(float2*)&ph[half][row][0] = make_float2(o0, o1);
            }
        }
        __syncthreads();
        if (tid < 100) {
            int j = tid;
            float2 r0p = *(float2*)&ph[0][j][0];
            float2 r1p = *(float2*)&ph[1][j][0];
            float2 z0p = *(float2*)&ph[0][100 + j][0];
            float2 z1p = *(float2*)&ph[1][100 + j][0];
            float2 n0p = *(float2*)&ph[0][200 + j][0];
            float2 n1p = *(float2*)&ph[1][200 + j][0];
            float hr0 = r0p.x + r1p.x, hr1 = r0p.y + r1p.y;
            float hz0 = z0p.x + z1p.x, hz1 = z0p.y + z1p.y;
            float hn0 = n0p.x + n1p.x, hn1 = n0p.y + n1p.y;
            float ho0 = hsh[0][j], ho1 = hsh[1][j];
            float r0 = sigf(xr0 + hr0), r1 = sigf(xr1 + hr1);
            float z0 = sigf(xz0 + hz0), z1 = sigf(xz1 + hz1);
            float n0 = tanh_fast(xn0 + r0 * hn0);
            float n1 = tanh_fast(xn1 + r1 * hn1);
            float hx = (1.f - z0) * n0 + z0 * ho0;
            float hy = (1.f - z1) * n1 + z1 * ho1;
            hsh[0][j] = hx;
            hsh[1][j] = hy;
            g_rnn[((size_t)b0 * Tz + t) * Hz + j]       = hx;
            g_rnn[((size_t)(b0 + 1) * Tz + t) * Hz + j] = hy;
            xr0 = nr0; xz0 = nz0; xn0 = nn0;
            xr1 = nr1; xz1 = nz1; xn1 = nn1;
        }
        __syncthreads();
    }
}

// ---------------- K4: per-(b,t) z (attention gate) and lgr_in ----------------
__global__ void __launch_bounds__(256) zli_kernel(const float* __restrict__ Wlgr,
                                                  const int* __restrict__ lens) {
    int warp = (blockIdx.x * 256 + threadIdx.x) >> 5;
    int lane = threadIdx.x & 31;
    if (warp >= BT) return;
    int b = warp >> 9;
    int t = warp & (Tz - 1);
    const float* r = g_rnn + (size_t)warp * Hz;
    float s1 = 0.f, s2 = 0.f, s3 = 0.f;
    for (int k = lane; k < Hz; k += 32) {
        float v = r[k];
        s1 += v;
        s2 += v * v;
        s3 += v * Wlgr[k];
    }
    #pragma unroll
    for (int o = 16; o > 0; o >>= 1) {
        s1 += __shfl_xor_sync(0xffffffffu, s1, o);
        s2 += __shfl_xor_sync(0xffffffffu, s2, o);
        s3 += __shfl_xor_sync(0xffffffffu, s3, o);
    }
    if (lane == 0) {
        float nrm = sqrtf(s2);
        float att = 0.001f * s1 / fmaxf(nrm, 1e-12f);
        float zv = (t < lens[b] && att > 0.f) ? att : 0.f;
        g_z[warp]  = zv;
        g_li[warp] = s3;
    }
}

// ============================================================================
// K6: second recurrence v3 (R13 best) — two independent batch groups with
// NAMED barriers. 128 blocks, 320 threads = 2 groups x 160.
// ============================================================================
__global__ void __launch_bounds__(320, 1) rec_kernel(const float* __restrict__ Wts,
                                                     const float* __restrict__ bts,
                                                     const float* __restrict__ Wlgr,
                                                     const float* __restrict__ blgr) {
    __shared__ __align__(16) float stsh[2][104];    // [group][k]
    __shared__ float li_sh[2][Tz];
    __shared__ float z_sh[2][Tz];
    __shared__ float gz[2][2];                      // [group][{gate,z}]
    const int tid = threadIdx.x;
    const int g  = (tid >= 160) ? 1 : 0;
    const int lt = tid - g * 160;
    const int b0 = blockIdx.x * 2;
    const int bb = b0 + g;

    for (int i = tid; i < Tz; i += 320) {
        li_sh[0][i] = g_li[(size_t)b0 * Tz + i];
        li_sh[1][i] = g_li[(size_t)(b0 + 1) * Tz + i];
        z_sh[0][i]  = g_z[(size_t)b0 * Tz + i];
        z_sh[1][i]  = g_z[(size_t)(b0 + 1) * Tz + i];
    }
    if (tid < 104) { stsh[0][tid] = 0.f; stsh[1][tid] = 0.f; }

    ull w[50];
    float btsr = 0.f, tv = 0.f, tn = 0.f;
    const float* tb = nullptr;
    if (lt < 100) {
        const ull* wp = (const ull*)(Wts + lt * 100);
        #pragma unroll
        for (int q = 0; q < 50; q++) w[q] = wp[q];
        btsr = bts[lt];
        tb = g_ti + (size_t)bb * Tz * Hz + lt;
        tv = tb[0];
        tn = tb[Hz];
    }
    float wl4[4] = {0.f, 0.f, 0.f, 0.f};
    float blg = 0.f;
    const int glan = lt - 128;
    if (lt >= 128) {
        #pragma unroll
        for (int i = 0; i < 4; i++) {
            int k = glan + 32 * i;
            wl4[i] = (k < 100) ? Wlgr[100 + k] : 0.f;
        }
        blg = blgr[0];
    }
    __syncthreads();

    for (int t = 0; t < Tz; t++) {
        float m = 0.f, tn2 = 0.f;
        if (lt < 100) {
            if (t + 2 < Tz) tn2 = tb[(size_t)(t + 2) * Hz];
            ull aA = 0ull, aB = 0ull;
            const ulonglong2* S = (const ulonglong2*)&stsh[g][0];
            #pragma unroll
            for (int v = 0; v < 25; v++) {
                ulonglong2 s = S[v];
                fma2(aA, w[2 * v],     s.x);
                fma2(aB, w[2 * v + 1], s.y);
            }
            m = upksum(aA) + upksum(aB);
        } else if (lt >= 128) {
            float pg = 0.f;
            #pragma unroll
            for (int i = 0; i < 4; i++) {
                int k = glan + 32 * i;
                if (k < 100) pg += wl4[i] * stsh[g][k];
            }
            #pragma unroll
            for (int o = 16; o > 0; o >>= 1)
                pg += __shfl_xor_sync(0xffffffffu, pg, o);
            if (glan == 0) {
                gz[g][0] = sigf(li_sh[g][t] + pg + blg);
                gz[g][1] = z_sh[g][t];
            }
        }
        named_bar(1 + g, 160);
        if (lt < 100) {
            float gg = gz[g][0], zz = gz[g][1];
            float s = stsh[g][lt];
            float ns = tanh_fast(tv + gg * m + btsr);
            stsh[g][lt] = (1.f - zz) * s + zz * ns;
            tv = tn; tn = tn2;
        }
        named_bar(1 + g, 160);
    }

    if (lt < 100)
        g_state[bb * Hz + lt] = stsh[g][lt];
}

// ---------------- K7: output projection ----------------
__global__ void __launch_bounds__(256) out_kernel(const float* __restrict__ Wout,
                                                  const float* __restrict__ bout,
                                                  float* __restrict__ out) {
    int idx = blockIdx.x * 256 + threadIdx.x;
    if (idx >= Bz * NCz) return;
    int b = idx / NCz, c = idx % NCz;
    float acc = bout[c];
    const float* s = g_state + b * Hz;
    const float* wr = Wout + c * Hz;
    #pragma unroll
    for (int k = 0; k < Hz; k++) acc += s[k] * wr[k];
    out[idx] = acc;
}

// ---------------- launch ----------------
extern "C" void kernel_launch(void* const* d_in, const int* in_sizes, int n_in,
                              void* d_out, int out_size) {
    const int*   txt   = (const int*)d_in[0];
    const int*   lens  = (const int*)d_in[1];
    const float* emb   = (const float*)d_in[2];
    const float* W_ih  = (const float*)d_in[3];
    const float* W_hh  = (const float*)d_in[4];
    const float* b_ih  = (const float*)d_in[5];
    const float* b_hh  = (const float*)d_in[6];
    const float* W_lgr = (const float*)d_in[7];
    const float* b_lgr = (const float*)d_in[8];
    const float* W_ts  = (const float*)d_in[9];
    const float* b_ts  = (const float*)d_in[10];
    const float* W_ti  = (const float*)d_in[11];
    const float* b_ti  = (const float*)d_in[12];
    const float* W_out = (const float*)d_in[13];
    const float* b_out = (const float*)d_in[14];
    float* out = (float*)d_out;

    float* xp  = nullptr; cudaGetSymbolAddress((void**)&xp,  g_xp);
    float* rnn = nullptr; cudaGetSymbolAddress((void**)&rnn, g_rnn);
    float* ti  = nullptr; cudaGetSymbolAddress((void**)&ti,  g_ti);

    scale_kernel<<<BT / 8, 256>>>(txt, emb);

    // two dummies: K2 becomes our 4th launch = ncu capture slot
    dummy_kernel<<<1, 32>>>();
    dummy_kernel<<<1, 32>>>();

    // K2: xp = norm(emb[txt]) @ W_ih^T + b_ih  — 2 K-panels, 2 CTAs/SM
    {
        constexpr int SMEM = (64 + 160) * 108 * 4;   // 96768 B
        cudaFuncSetAttribute(
            (const void*)mma_gemm_kernel<200, 100, 2, 104, 108, 160, 40, true>,
            cudaFuncAttributeMaxDynamicSharedMemorySize, SMEM);
        dim3 grid(BT / 64, 2);
        mma_gemm_kernel<200, 100, 2, 104, 108, 160, 40, true><<<grid, 256, SMEM>>>(
            nullptr, txt, emb, W_ih, b_ih, xp, 300);
    }

    gru_kernel<<<Bz / 2, 640>>>(W_hh, b_hh);

    zli_kernel<<<BT / 8, 256>>>(W_lgr, lens);

    // K5: ti = rnn @ W_ti^T + b_ti  — single panel
    {
        constexpr int SMEM = (64 + 128) * 108 * 4;
        cudaFuncSetAttribute(
            (const void*)mma_gemm_kernel<100, 100, 1, 104, 108, 128, 32, false>,
            cudaFuncAttributeMaxDynamicSharedMemorySize, SMEM);
        dim3 grid(BT / 64, 1);
        mma_gemm_kernel<100, 100, 1, 104, 108, 128, 32, false><<<grid, 256, SMEM>>>(
            rnn, nullptr, nullptr, W_ti, b_ti, ti, 100);
    }

    rec_kernel<<<Bz / 2, 320>>>(W_ts, b_ts, W_lgr, b_lgr);

    out_kernel<<<(Bz * NCz + 255) / 256, 256>>>(W_out, b_out, out);
}

// round 17
// speedup vs baseline: 1.1685x; 1.0642x over previous
#include <cuda_runtime.h>
#include <cstdint>

#define Bz   256
#define Tz   512
#define Ez   200
#define Hz   100
#define NCz  5
#define BT   131072      // B*T

typedef unsigned long long ull;

// ---------------- scratch ----------------
__device__ float g_scale[BT];
__device__ float g_xp[(size_t)BT * 300];   // 157 MB
__device__ float g_rnn[(size_t)BT * 100];  // 52 MB
__device__ float g_ti[(size_t)BT * 100];   // 52 MB
__device__ float g_z[BT];
__device__ float g_li[BT];
__device__ float g_state[Bz * Hz];

// ---------------- helpers ----------------
__device__ __forceinline__ float sigf(float x) {
    return 1.0f / (1.0f + __expf(-x));
}
__device__ __forceinline__ float tanh_fast(float x) {
    float t = __expf(-2.0f * fabsf(x));
    float r = (1.0f - t) / (1.0f + t);
    return copysignf(r, x);
}
__device__ __forceinline__ float to_tf32(float x) {
    uint32_t u;
    asm("cvt.rna.tf32.f32 %0, %1;" : "=r"(u) : "f"(x));
    return __uint_as_float(u);
}
__device__ __forceinline__ void fma2(ull& d, ull a, ull b) {
    asm("fma.rn.f32x2 %0, %1, %2, %0;" : "+l"(d) : "l"(a), "l"(b));
}
__device__ __forceinline__ float upksum(ull v) {
    float lo, hi;
    asm("mov.b64 {%0,%1}, %2;" : "=f"(lo), "=f"(hi) : "l"(v));
    return lo + hi;
}
__device__ __forceinline__ void named_bar(int id, int cnt) {
    asm volatile("bar.sync %0, %1;" :: "r"(id), "r"(cnt) : "memory");
}

// ---------------- K1: per-row embedding norm scale ----------------
__global__ void __launch_bounds__(256) scale_kernel(const int* __restrict__ txt,
                                                    const float* __restrict__ emb) {
    int warp = (blockIdx.x * 256 + threadIdx.x) >> 5;
    int lane = threadIdx.x & 31;
    if (warp >= BT) return;
    int tok = txt[warp];
    const float* row = emb + (size_t)tok * Ez;
    float ss = 0.f;
    for (int k = lane; k < Ez; k += 32) { float v = row[k]; ss += v * v; }
    #pragma unroll
    for (int o = 16; o > 0; o >>= 1) ss += __shfl_xor_sync(0xffffffffu, ss, o);
    if (lane == 0) {
        float n = sqrtf(ss);
        g_scale[warp] = (n > 1.0f) ? 1.0f / (n + 1e-7f) : 1.0f;
    }
}

// ---------------- dummy (shifts ncu capture slot) ----------------
__global__ void dummy_kernel() {}

// ---------------- K2/K5: tf32 MMA GEMM with K-panels ----------------
// NPAN panels of PANK floats each; panel fill clamps to min(KDIM-kbase, PANK)
// so panels never overlap. KSTR=60 -> small smem -> 4 CTAs/SM.
template <int KDIM, int PANK, int NPAN, int KCEIL, int KSTR, int TN, int WNc, bool GATHER>
__global__ void __launch_bounds__(256) mma_gemm_kernel(
    const float* __restrict__ Ain,
    const int* __restrict__ txt,
    const float* __restrict__ emb,
    const float* __restrict__ W,
    const float* __restrict__ bias,
    float* __restrict__ C,
    int NV)
{
    extern __shared__ float sm[];
    float* As = sm;
    float* Bs = sm + 64 * KSTR;
    __shared__ int   s_tok[64];
    __shared__ float s_scl[64];

    const int tid   = threadIdx.x;
    const int rbase = blockIdx.x * 64;
    const int nbase = blockIdx.y * TN;

    if (GATHER) {
        if (tid < 64) {
            int r = rbase + tid;
            s_tok[tid] = txt[r];
            s_scl[tid] = g_scale[r];
        }
        __syncthreads();
    }

    const int wid  = tid >> 5;
    const int lane = tid & 31;
    const int g    = lane >> 2;
    const int tg   = lane & 3;
    const int mwarp = wid & 1;
    const int nwarp = wid >> 1;
    const int NF = WNc / 8;

    float c[2][NF][4];
    #pragma unroll
    for (int mt = 0; mt < 2; mt++)
        #pragma unroll
        for (int nf = 0; nf < NF; nf++)
            #pragma unroll
            for (int i = 0; i < 4; i++) c[mt][nf][i] = 0.f;

    const int K4 = KCEIL / 4;

    #pragma unroll 1
    for (int kp = 0; kp < NPAN; kp++) {
        const int kbase = kp * PANK;
        int rem = KDIM - kbase;                    // floats valid in this panel
        if (rem > PANK) rem = PANK;                // <-- no panel overlap!
        // ---- fill A panel ----
        for (int e = tid; e < 64 * K4; e += 256) {
            int row = e / K4, k4 = e % K4;
            float4 v = make_float4(0.f, 0.f, 0.f, 0.f);
            if (4 * k4 + 3 < rem) {
                if (GATHER) {
                    const float4* p = (const float4*)(emb + (size_t)s_tok[row] * KDIM + kbase) + k4;
                    v = *p;
                    float s = s_scl[row];
                    v.x *= s; v.y *= s; v.z *= s; v.w *= s;
                } else {
                    const float4* p = (const float4*)(Ain + (size_t)(rbase + row) * KDIM + kbase) + k4;
                    v = *p;
                }
            }
            float4 o = make_float4(to_tf32(v.x), to_tf32(v.y), to_tf32(v.z), to_tf32(v.w));
            *(float4*)(As + row * KSTR + 4 * k4) = o;
        }
        // ---- fill B panel ----
        for (int e = tid; e < TN * K4; e += 256) {
            int n = e / K4, k4 = e % K4;
            int ng = nbase + n;
            float4 v = make_float4(0.f, 0.f, 0.f, 0.f);
            if (ng < NV && 4 * k4 + 3 < rem) {
                const float4* p = (const float4*)(W + (size_t)ng * KDIM + kbase) + k4;
                v = *p;
            }
            float4 o = make_float4(to_tf32(v.x), to_tf32(v.y), to_tf32(v.z), to_tf32(v.w));
            *(float4*)(Bs + n * KSTR + 4 * k4) = o;
        }
        __syncthreads();

        const float* Aw = As + (mwarp * 32) * KSTR;
        const float* Bw = Bs + (nwarp * WNc) * KSTR;

        #pragma unroll 1
        for (int k8 = 0; k8 < KCEIL / 8; k8++) {
            int k0 = k8 * 8;
            uint32_t a[2][4], b[NF][2];
            #pragma unroll
            for (int mt = 0; mt < 2; mt++) {
                const float* ap = Aw + (mt * 16 + g) * KSTR + k0 + tg;
                a[mt][0] = __float_as_uint(ap[0]);
                a[mt][1] = __float_as_uint(ap[8 * KSTR]);
                a[mt][2] = __float_as_uint(ap[4]);
                a[mt][3] = __float_as_uint(ap[8 * KSTR + 4]);
            }
            #pragma unroll
            for (int nf = 0; nf < NF; nf++) {
                const float* bp = Bw + (nf * 8 + g) * KSTR + k0 + tg;
                b[nf][0] = __float_as_uint(bp[0]);
                b[nf][1] = __float_as_uint(bp[4]);
            }
            #pragma unroll
            for (int mt = 0; mt < 2; mt++)
                #pragma unroll
                for (int nf = 0; nf < NF; nf++) {
                    asm volatile(
                        "mma.sync.aligned.m16n8k8.row.col.f32.tf32.tf32.f32 "
                        "{%0,%1,%2,%3}, {%4,%5,%6,%7}, {%8,%9}, {%0,%1,%2,%3};"
                        : "+f"(c[mt][nf][0]), "+f"(c[mt][nf][1]),
                          "+f"(c[mt][nf][2]), "+f"(c[mt][nf][3])
                        : "r"(a[mt][0]), "r"(a[mt][1]), "r"(a[mt][2]), "r"(a[mt][3]),
                          "r"(b[nf][0]), "r"(b[nf][1]));
                }
        }
        __syncthreads();
    }

    #pragma unroll
    for (int mt = 0; mt < 2; mt++) {
        int row = rbase + mwarp * 32 + mt * 16 + g;
        #pragma unroll
        for (int nf = 0; nf < NF; nf++) {
            int col = nbase + nwarp * WNc + nf * 8 + 2 * tg;
            if (col < NV) {
                float b0 = bias[col], b1 = bias[col + 1];
                float2 v0 = make_float2(c[mt][nf][0] + b0, c[mt][nf][1] + b1);
                float2 v1 = make_float2(c[mt][nf][2] + b0, c[mt][nf][3] + b1);
                *(float2*)(C + (size_t)row * NV + col) = v0;
                *(float2*)(C + (size_t)(row + 8) * NV + col) = v1;
            }
        }
    }
}

// ============================================================================
// K3: GRU scan v6 (best) — warp-granular k-split + packed ph exchange.
// ============================================================================
__global__ void __launch_bounds__(640, 1) gru_kernel(const float* __restrict__ Whh,
                                                     const float* __restrict__ bhh) {
    __shared__ __align__(16) float hsh[2][104];     // [batch][k]
    __shared__ __align__(16) float ph[2][304][2];   // [half][row][{b0,b1}]
    const int tid = threadIdx.x;
    const int b0 = blockIdx.x * 2;
    const float* x0 = g_xp + (size_t)b0 * Tz * 300;
    const float* x1 = x0 + (size_t)Tz * 300;

    const int half = (tid >= 320) ? 1 : 0;
    const int row  = tid - half * 320;              // 0..319
    const int rcl  = (row < 300) ? row : 299;
    const bool act = (row < 300);

    if (tid < 104) { hsh[0][tid] = 0.f; hsh[1][tid] = 0.f; }

    ull ws, wv[24];
    {
        const ull* p = (const ull*)(Whh + rcl * 100 + half * 50);
        if (half == 0) {
            ws = p[24];
            #pragma unroll
            for (int q = 0; q < 24; q++) wv[q] = p[q];
        } else {
            ws = p[0];
            #pragma unroll
            for (int q = 0; q < 24; q++) wv[q] = p[1 + q];
        }
    }
    const int sidx = half ? 25 : 24;
    const int vec0 = half ? 26 : 0;
    float bias_r = (half == 0) ? bhh[rcl] : 0.f;

    float xr0 = 0.f, xz0 = 0.f, xn0 = 0.f, xr1 = 0.f, xz1 = 0.f, xn1 = 0.f;
    if (tid < 100) {
        xr0 = x0[tid]; xz0 = x0[100 + tid]; xn0 = x0[200 + tid];
        xr1 = x1[tid]; xz1 = x1[100 + tid]; xn1 = x1[200 + tid];
    }
    __syncthreads();

    for (int t = 0; t < Tz; t++) {
        float nr0 = 0.f, nz0 = 0.f, nn0 = 0.f, nr1 = 0.f, nz1 = 0.f, nn1 = 0.f;
        if (tid < 100 && t + 1 < Tz) {
            const float* p0 = x0 + (size_t)(t + 1) * 300;
            const float* p1 = x1 + (size_t)(t + 1) * 300;
            nr0 = p0[tid]; nz0 = p0[100 + tid]; nn0 = p0[200 + tid];
            nr1 = p1[tid]; nz1 = p1[100 + tid]; nn1 = p1[200 + tid];
        }
        {
            const ull* B0 = (const ull*)&hsh[0][0];
            const ull* B1 = B0 + 52;
            ull a0 = 0ull, d0 = 0ull, a1 = 0ull, d1 = 0ull;
            fma2(a0, ws, B0[sidx]);
            fma2(a1, ws, B1[sidx]);
            const ulonglong2* V0 = (const ulonglong2*)(B0 + vec0);
            const ulonglong2* V1 = (const ulonglong2*)(B1 + vec0);
            #pragma unroll
            for (int q = 0; q < 12; q++) {
                ulonglong2 h0 = V0[q], h1 = V1[q];
                fma2(a0, wv[2 * q],     h0.x);
                fma2(d0, wv[2 * q + 1], h0.y);
                fma2(a1, wv[2 * q],     h1.x);
                fma2(d1, wv[2 * q + 1], h1.y);
            }
            if (act) {
                float o0 = upksum(a0) + upksum(d0) + bias_r;
                float o1 = upksum(a1) + upksum(d1) + bias_r;
                *(float2*)&ph[half][row][0] = make_float2(o0, o1);
            }
        }
        __syncthreads();
        if (tid < 100) {
            int j = tid;
            float2 r0p = *(float2*)&ph[0][j][0];
            float2 r1p = *(float2*)&ph[1][j][0];
            float2 z0p = *(float2*)&ph[0][100 + j][0];
            float2 z1p = *(float2*)&ph[1][100 + j][0];
            float2 n0p = *(float2*)&ph[0][200 + j][0];
            float2 n1p = *(float2*)&ph[1][200 + j][0];
            float hr0 = r0p.x + r1p.x, hr1 = r0p.y + r1p.y;
            float hz0 = z0p.x + z1p.x, hz1 = z0p.y + z1p.y;
            float hn0 = n0p.x + n1p.x, hn1 = n0p.y + n1p.y;
            float ho0 = hsh[0][j], ho1 = hsh[1][j];
            float r0 = sigf(xr0 + hr0), r1 = sigf(xr1 + hr1);
            float z0 = sigf(xz0 + hz0), z1 = sigf(xz1 + hz1);
            float n0 = tanh_fast(xn0 + r0 * hn0);
            float n1 = tanh_fast(xn1 + r1 * hn1);
            float hx = (1.f - z0) * n0 + z0 * ho0;
            float hy = (1.f - z1) * n1 + z1 * ho1;
            hsh[0][j] = hx;
            hsh[1][j] = hy;
            g_rnn[((size_t)b0 * Tz + t) * Hz + j]       = hx;
            g_rnn[((size_t)(b0 + 1) * Tz + t) * Hz + j] = hy;
            xr0 = nr0; xz0 = nz0; xn0 = nn0;
            xr1 = nr1; xz1 = nz1; xn1 = nn1;
        }
        __syncthreads();
    }
}

// ---------------- K4: per-(b,t) z (attention gate) and lgr_in ----------------
__global__ void __launch_bounds__(256) zli_kernel(const float* __restrict__ Wlgr,
                                                  const int* __restrict__ lens) {
    int warp = (blockIdx.x * 256 + threadIdx.x) >> 5;
    int lane = threadIdx.x & 31;
    if (warp >= BT) return;
    int b = warp >> 9;
    int t = warp & (Tz - 1);
    const float* r = g_rnn + (size_t)warp * Hz;
    float s1 = 0.f, s2 = 0.f, s3 = 0.f;
    for (int k = lane; k < Hz; k += 32) {
        float v = r[k];
        s1 += v;
        s2 += v * v;
        s3 += v * Wlgr[k];
    }
    #pragma unroll
    for (int o = 16; o > 0; o >>= 1) {
        s1 += __shfl_xor_sync(0xffffffffu, s1, o);
        s2 += __shfl_xor_sync(0xffffffffu, s2, o);
        s3 += __shfl_xor_sync(0xffffffffu, s3, o);
    }
    if (lane == 0) {
        float nrm = sqrtf(s2);
        float att = 0.001f * s1 / fmaxf(nrm, 1e-12f);
        float zv = (t < lens[b] && att > 0.f) ? att : 0.f;
        g_z[warp]  = zv;
        g_li[warp] = s3;
    }
}

// ============================================================================
// K6: second recurrence v3 (best) — two independent batch groups with
// NAMED barriers. 128 blocks, 320 threads = 2 groups x 160.
// ============================================================================
__global__ void __launch_bounds__(320, 1) rec_kernel(const float* __restrict__ Wts,
                                                     const float* __restrict__ bts,
                                                     const float* __restrict__ Wlgr,
                                                     const float* __restrict__ blgr) {
    __shared__ __align__(16) float stsh[2][104];    // [group][k]
    __shared__ float li_sh[2][Tz];
    __shared__ float z_sh[2][Tz];
    __shared__ float gz[2][2];                      // [group][{gate,z}]
    const int tid = threadIdx.x;
    const int g  = (tid >= 160) ? 1 : 0;
    const int lt = tid - g * 160;
    const int b0 = blockIdx.x * 2;
    const int bb = b0 + g;

    for (int i = tid; i < Tz; i += 320) {
        li_sh[0][i] = g_li[(size_t)b0 * Tz + i];
        li_sh[1][i] = g_li[(size_t)(b0 + 1) * Tz + i];
        z_sh[0][i]  = g_z[(size_t)b0 * Tz + i];
        z_sh[1][i]  = g_z[(size_t)(b0 + 1) * Tz + i];
    }
    if (tid < 104) { stsh[0][tid] = 0.f; stsh[1][tid] = 0.f; }

    ull w[50];
    float btsr = 0.f, tv = 0.f, tn = 0.f;
    const float* tb = nullptr;
    if (lt < 100) {
        const ull* wp = (const ull*)(Wts + lt * 100);
        #pragma unroll
        for (int q = 0; q < 50; q++) w[q] = wp[q];
        btsr = bts[lt];
        tb = g_ti + (size_t)bb * Tz * Hz + lt;
        tv = tb[0];
        tn = tb[Hz];
    }
    float wl4[4] = {0.f, 0.f, 0.f, 0.f};
    float blg = 0.f;
    const int glan = lt - 128;
    if (lt >= 128) {
        #pragma unroll
        for (int i = 0; i < 4; i++) {
            int k = glan + 32 * i;
            wl4[i] = (k < 100) ? Wlgr[100 + k] : 0.f;
        }
        blg = blgr[0];
    }
    __syncthreads();

    for (int t = 0; t < Tz; t++) {
        float m = 0.f, tn2 = 0.f;
        if (lt < 100) {
            if (t + 2 < Tz) tn2 = tb[(size_t)(t + 2) * Hz];
            ull aA = 0ull, aB = 0ull;
            const ulonglong2* S = (const ulonglong2*)&stsh[g][0];
            #pragma unroll
            for (int v = 0; v < 25; v++) {
                ulonglong2 s = S[v];
                fma2(aA, w[2 * v],     s.x);
                fma2(aB, w[2 * v + 1], s.y);
            }
            m = upksum(aA) + upksum(aB);
        } else if (lt >= 128) {
            float pg = 0.f;
            #pragma unroll
            for (int i = 0; i < 4; i++) {
                int k = glan + 32 * i;
                if (k < 100) pg += wl4[i] * stsh[g][k];
            }
            #pragma unroll
            for (int o = 16; o > 0; o >>= 1)
                pg += __shfl_xor_sync(0xffffffffu, pg, o);
            if (glan == 0) {
                gz[g][0] = sigf(li_sh[g][t] + pg + blg);
                gz[g][1] = z_sh[g][t];
            }
        }
        named_bar(1 + g, 160);
        if (lt < 100) {
            float gg = gz[g][0], zz = gz[g][1];
            float s = stsh[g][lt];
            float ns = tanh_fast(tv + gg * m + btsr);
            stsh[g][lt] = (1.f - zz) * s + zz * ns;
            tv = tn; tn = tn2;
        }
        named_bar(1 + g, 160);
    }

    if (lt < 100)
        g_state[bb * Hz + lt] = stsh[g][lt];
}

// ---------------- K7: output projection ----------------
__global__ void __launch_bounds__(256) out_kernel(const float* __restrict__ Wout,
                                                  const float* __restrict__ bout,
                                                  float* __restrict__ out) {
    int idx = blockIdx.x * 256 + threadIdx.x;
    if (idx >= Bz * NCz) return;
    int b = idx / NCz, c = idx % NCz;
    float acc = bout[c];
    const float* s = g_state + b * Hz;
    const float* wr = Wout + c * Hz;
    #pragma unroll
    for (int k = 0; k < Hz; k++) acc += s[k] * wr[k];
    out[idx] = acc;
}

// ---------------- launch ----------------
extern "C" void kernel_launch(void* const* d_in, const int* in_sizes, int n_in,
                              void* d_out, int out_size) {
    const int*   txt   = (const int*)d_in[0];
    const int*   lens  = (const int*)d_in[1];
    const float* emb   = (const float*)d_in[2];
    const float* W_ih  = (const float*)d_in[3];
    const float* W_hh  = (const float*)d_in[4];
    const float* b_ih  = (const float*)d_in[5];
    const float* b_hh  = (const float*)d_in[6];
    const float* W_lgr = (const float*)d_in[7];
    const float* b_lgr = (const float*)d_in[8];
    const float* W_ts  = (const float*)d_in[9];
    const float* b_ts  = (const float*)d_in[10];
    const float* W_ti  = (const float*)d_in[11];
    const float* b_ti  = (const float*)d_in[12];
    const float* W_out = (const float*)d_in[13];
    const float* b_out = (const float*)d_in[14];
    float* out = (float*)d_out;

    float* xp  = nullptr; cudaGetSymbolAddress((void**)&xp,  g_xp);
    float* rnn = nullptr; cudaGetSymbolAddress((void**)&rnn, g_rnn);
    float* ti  = nullptr; cudaGetSymbolAddress((void**)&ti,  g_ti);

    scale_kernel<<<BT / 8, 256>>>(txt, emb);

    // two dummies: K2 stays in ncu's capture slot (4th launch)
    dummy_kernel<<<1, 32>>>();
    dummy_kernel<<<1, 32>>>();

    // K2: xp = norm(emb[txt]) @ W_ih^T + b_ih — 4 K-panels of 52, 4 CTAs/SM
    {
        constexpr int SMEM = (64 + 160) * 60 * 4;   // 53760 B
        cudaFuncSetAttribute(
            (const void*)mma_gemm_kernel<200, 52, 4, 56, 60, 160, 40, true>,
            cudaFuncAttributeMaxDynamicSharedMemorySize, SMEM);
        dim3 grid(BT / 64, 2);
        mma_gemm_kernel<200, 52, 4, 56, 60, 160, 40, true><<<grid, 256, SMEM>>>(
            nullptr, txt, emb, W_ih, b_ih, xp, 300);
    }

    gru_kernel<<<Bz / 2, 640>>>(W_hh, b_hh);

    zli_kernel<<<BT / 8, 256>>>(W_lgr, lens);

    // K5: ti = rnn @ W_ti^T + b_ti — 2 K-panels of 52, 4 CTAs/SM
    {
        constexpr int SMEM = (64 + 128) * 60 * 4;   // 46080 B
        cudaFuncSetAttribute(
            (const void*)mma_gemm_kernel<100, 52, 2, 56, 60, 128, 32, false>,
            cudaFuncAttributeMaxDynamicSharedMemorySize, SMEM);
        dim3 grid(BT / 64, 1);
        mma_gemm_kernel<100, 52, 2, 56, 60, 128, 32, false><<<grid, 256, SMEM>>>(
            rnn, nullptr, nullptr, W_ti, b_ti, ti, 100);
    }

    rec_kernel<<<Bz / 2, 320>>>(W_ts, b_ts, W_lgr, b_lgr);

    out_kernel<<<(Bz * NCz + 255) / 256, 256>>>(W_out, b_out, out);
}